// round 15
// baseline (speedup 1.0000x reference)
#include <cuda_runtime.h>
#include <cuda_bf16.h>
#include <cstdint>

#define BATCH 4
#define SEQL  1024
#define CH    512
#define KW    5
#define DI    1024
#define DS    16
#define DTR   32
#define BL    (BATCH*SEQL)
#define XZW   (2*DI)

#define BK  64
#define KST 72   // BK + 8 pad (bf16 elems), 144B row stride

typedef __nv_bfloat16 bf;

// ---------------- scratch ----------------
__device__ bf    g_h[BL*CH];
__device__ float g_tmp[2ull*BL*CH];           // split-K partials (conv / final)
__device__ bf    g_xz[2ull*BL*XZW];
__device__ bf    g_u[2ull*BL*DI];
__device__ float g_delta[2ull*BL*DI];
__device__ float g_xdbc[4ull*BL*64];          // [dir][kh][BL][64] split-K partials
__device__ float g_xs[2ull*BL*64];            // combined B/C for scan
__device__ bf    g_y[(size_t)BL*2048];        // [row][dir*1024+d]
__device__ bf    g_cwt[3ull*KW*CH*CH];        // [layer][k][co][ci]
__device__ bf    g_inw[2ull*XZW*CH];
__device__ bf    g_xw[2ull*64*DI];
__device__ bf    g_owT[2ull*DI*CH];           // transposed out-proj weights [dir][e][k]
__device__ bf    g_projw[(size_t)CH*2*CH];
__device__ bf    g_wfuse[(size_t)CH*2048];    // [c][dir*1024+e]

// ---------------- helpers ----------------
__device__ __forceinline__ float siluf(float x) { return x / (1.0f + __expf(-x)); }
__device__ __forceinline__ float softplusf(float x) {
    return fmaxf(x, 0.0f) + log1pf(__expf(-fabsf(x)));
}
__device__ __forceinline__ void cp16u(uint32_t d, const void* s) {
    asm volatile("cp.async.cg.shared.global [%0], [%1], 16;" :: "r"(d), "l"(s));
}
__device__ __forceinline__ void cp16z(uint32_t d, const void* s, int valid) {
    int sz = valid ? 16 : 0;
    asm volatile("cp.async.cg.shared.global [%0], [%1], 16, %2;" :: "r"(d), "l"(s), "r"(sz));
}
__device__ __forceinline__ void cpcommit() { asm volatile("cp.async.commit_group;"); }
template<int N> __device__ __forceinline__ void cpwait() {
    asm volatile("cp.async.wait_group %0;" :: "n"(N));
}
__device__ __forceinline__ void ldsm4(uint32_t* r, uint32_t a) {
    asm volatile("ldmatrix.sync.aligned.m8n8.x4.shared.b16 {%0,%1,%2,%3}, [%4];"
        : "=r"(r[0]), "=r"(r[1]), "=r"(r[2]), "=r"(r[3]) : "r"(a));
}
__device__ __forceinline__ void mma16(float* d, const uint32_t* a, const uint32_t* b) {
    asm volatile(
        "mma.sync.aligned.m16n8k16.row.col.f32.bf16.bf16.f32 "
        "{%0,%1,%2,%3}, {%4,%5,%6,%7}, {%8,%9}, {%0,%1,%2,%3};"
        : "+f"(d[0]), "+f"(d[1]), "+f"(d[2]), "+f"(d[3])
        : "r"(a[0]), "r"(a[1]), "r"(a[2]), "r"(a[3]), "r"(b[0]), "r"(b[1]));
}

// ---------------- merged weight conversion ----------------
struct CvtP { const float* s[5]; bf* d[5]; const float* owf; const float* owb; };
__global__ void cvt_all(const float* __restrict__ conv_w, CvtP p) {
    __shared__ float s[64*65];
    int bx = blockIdx.x;
    if (bx < 3*CH) {
        int co = bx & 511, layer = bx >> 9;
        const float* src = conv_w + (size_t)bx * (CH*KW);
        for (int i = threadIdx.x; i < CH*KW; i += 256) s[i] = src[i];
        __syncthreads();
        bf* dst = g_cwt + (size_t)layer * KW * CH * CH;
        for (int i = threadIdx.x; i < CH*KW; i += 256) {
            int k = i >> 9, ci = i & 511;
            dst[(size_t)k*CH*CH + (size_t)co*CH + ci] = __float2bfloat16(s[ci*KW + k]);
        }
    } else if (bx < 3*CH + 256) {
        int idx = bx - 3*CH;
        int dir = idx >> 7;
        int te = (idx & 127) >> 3, tk = idx & 7;
        const float* ow = dir ? p.owb : p.owf;
        for (int i = threadIdx.x; i < 4096; i += 256) {
            int kk = i >> 6, ee = i & 63;
            s[kk*65 + ee] = ow[(size_t)(tk*64 + kk)*DI + te*64 + ee];
        }
        __syncthreads();
        bf* dst = g_owT + (size_t)dir*DI*CH;
        for (int i = threadIdx.x; i < 4096; i += 256) {
            int ee = i >> 6, kk = i & 63;
            dst[(size_t)(te*64 + ee)*CH + tk*64 + kk] = __float2bfloat16(s[kk*65 + ee]);
        }
    } else {
        const int sz[5] = {262144, 262144, 16384, 16384, 131072};
        int i = (bx - 3*CH - 256) * 256 + threadIdx.x;
        int seg = 0;
#pragma unroll
        for (int q = 0; q < 5; q++) {
            if (seg == q && i >= sz[q]) { i -= sz[q]; seg = q + 1; }
        }
        if (seg >= 5) return;
        float4 v = ((const float4*)p.s[seg])[i];
        __nv_bfloat162* o = (__nv_bfloat162*)p.d[seg];
        o[i*2]   = __floats2bfloat162_rn(v.x, v.y);
        o[i*2+1] = __floats2bfloat162_rn(v.z, v.w);
    }
}

// ---------------- embedding ----------------
__global__ void embed_k(const int* __restrict__ x, const float* __restrict__ emb,
                        bf* __restrict__ out) {
    int i = blockIdx.x * blockDim.x + threadIdx.x;
    if (i >= BL * CH) return;
    int row = i >> 9, c = i & (CH - 1);
    out[i] = __float2bfloat16(emb[x[row] * CH + c]);
}

// ======== bf16 MMA GEMM, 128x128 tile, 8 warps (64x32 warp tile), 2-stage ========
// z-dim generic: A += z*az, Wt += z*wz, Out += z*oz. EPI: 0 bf16 out, 1 fp32 out
template <int EPI>
__global__ __launch_bounds__(256, 2)
void gemm256(const bf* __restrict__ A, const bf* __restrict__ Wt,
             void* __restrict__ OutV,
             int K, int lda, int ldw, int ldo, int revz,
             size_t az, size_t wz, size_t oz) {
    constexpr int SST = 256 * KST * 2;
    extern __shared__ char smem[];

    const int t = threadIdx.x, lane = t & 31, warp = t >> 5;
    const int wm = warp >> 2, wn = warp & 3;      // 2 x 4 warp grid, tile 64x32
    const int m0 = blockIdx.y * 128, n0 = blockIdx.x * 128;
    const int zz = blockIdx.z;
    A  += (size_t)zz * az;
    Wt += (size_t)zz * wz;
    const int rev = revz && zz;

    float acc[4][4][4];
#pragma unroll
    for (int i = 0; i < 4; i++)
#pragma unroll
        for (int j = 0; j < 4; j++)
#pragma unroll
            for (int q = 0; q < 4; q++) acc[i][j][q] = 0.0f;

    const int lr   = t >> 3;         // 0..31, rows lr + 32*i
    const int koff = (t & 7) * 8;
    int ga[4];
#pragma unroll
    for (int i = 0; i < 4; i++) {
        int r = m0 + lr + 32*i;
        ga[i] = rev ? ((r & ~(SEQL-1)) + (SEQL-1) - (r & (SEQL-1))) : r;
    }
    const uint32_t base = (uint32_t)__cvta_generic_to_shared(smem);
    const uint32_t a_st = base + lr * (KST*2) + koff*2;
    const uint32_t b_st = base + 128*(KST*2) + lr * (KST*2) + koff*2;
    const uint32_t a_off = ((wm*64 + ((lane>>3)&1)*8 + (lane&7)) * KST + (lane>>4)*8) * 2;
    const uint32_t b_off = (128*KST + (wn*32 + ((lane>>4)&1)*8 + (lane&7)) * KST
                            + ((lane>>3)&1)*8) * 2;

    auto load = [&](int st, int k0) {
#pragma unroll
        for (int i = 0; i < 4; i++)
            cp16u(a_st + i*32*(KST*2) + st*SST, A + (size_t)ga[i]*lda + k0 + koff);
#pragma unroll
        for (int i = 0; i < 4; i++)
            cp16u(b_st + i*32*(KST*2) + st*SST,
                  Wt + (size_t)(n0 + lr + i*32)*ldw + k0 + koff);
        cpcommit();
    };
    load(0, 0);
    load(1, BK);
    const int nch = K >> 6;
    for (int ch = 0; ch < nch; ch++) {
        cpwait<1>();
        __syncthreads();
        const uint32_t sb = base + (ch & 1) * SST;
#pragma unroll
        for (int ks = 0; ks < 4; ks++) {
            uint32_t af[4][4], bfr[2][4];
#pragma unroll
            for (int mf = 0; mf < 4; mf++)
                ldsm4(af[mf], sb + a_off + mf*16*KST*2 + ks*32);
            ldsm4(bfr[0], sb + b_off + ks*32);
            ldsm4(bfr[1], sb + b_off + 16*KST*2 + ks*32);
#pragma unroll
            for (int mf = 0; mf < 4; mf++)
#pragma unroll
                for (int nf = 0; nf < 4; nf++)
                    mma16(acc[mf][nf], af[mf], &bfr[nf>>1][(nf&1)*2]);
        }
        __syncthreads();
        if (ch + 2 < nch) load(ch & 1, (ch + 2) * BK);
    }
#pragma unroll
    for (int mf = 0; mf < 4; mf++) {
#pragma unroll
        for (int half = 0; half < 2; half++) {
            int r = m0 + wm*64 + mf*16 + (lane>>2) + half*8;
#pragma unroll
            for (int nf = 0; nf < 4; nf++) {
                int c = n0 + wn*32 + nf*8 + (lane&3)*2;
                float v0 = acc[mf][nf][half*2], v1 = acc[mf][nf][half*2+1];
                if (EPI == 0) {
                    bf* Ob = (bf*)OutV + (size_t)zz*oz;
                    *(__nv_bfloat162*)(Ob + (size_t)r*ldo + c) =
                        __floats2bfloat162_rn(v0, v1);
                } else {
                    float* Of = (float*)OutV + (size_t)zz*oz;
                    float2 f = {v0, v1};
                    *(float2*)(Of + (size_t)r*ldo + c) = f;
                }
            }
        }
    }
}

// ======== conv1d GEMM, 256 thr, 8 warps 64x32, split-K via blockIdx.z ========
__global__ __launch_bounds__(256, 2)
void conv256(const bf* __restrict__ In, const bf* __restrict__ Wl,
             float* __restrict__ Out) {
    constexpr int SST = 256 * KST * 2;
    extern __shared__ char smem[];
    const int t = threadIdx.x, lane = t & 31, warp = t >> 5;
    const int wm = warp >> 2, wn = warp & 3;
    const int m0 = blockIdx.y * 128, n0 = blockIdx.x * 128;
    const int kh = blockIdx.z;
    Out += (size_t)kh * BL * CH;

    float acc[4][4][4];
#pragma unroll
    for (int i = 0; i < 4; i++)
#pragma unroll
        for (int j = 0; j < 4; j++)
#pragma unroll
            for (int q = 0; q < 4; q++) acc[i][j][q] = 0.0f;

    const int lr   = t >> 3;
    const int koff = (t & 7) * 8;
    int gr[4], lc[4];
#pragma unroll
    for (int i = 0; i < 4; i++) {
        gr[i] = m0 + lr + 32*i;
        lc[i] = gr[i] & (SEQL - 1);
    }
    const uint32_t base = (uint32_t)__cvta_generic_to_shared(smem);
    const uint32_t a_st = base + lr * (KST*2) + koff*2;
    const uint32_t b_st = base + 128*(KST*2) + lr * (KST*2) + koff*2;
    const uint32_t a_off = ((wm*64 + ((lane>>3)&1)*8 + (lane&7)) * KST + (lane>>4)*8) * 2;
    const uint32_t b_off = (128*KST + (wn*32 + ((lane>>4)&1)*8 + (lane&7)) * KST
                            + ((lane>>3)&1)*8) * 2;

    auto load = [&](int st, int chg) {
        int kk = chg >> 3, ci0 = (chg & 7) << 6;
        int sh = kk - 2;
#pragma unroll
        for (int i = 0; i < 4; i++) {
            int v = (unsigned)(lc[i] + sh) < (unsigned)SEQL;
            int rr = v ? gr[i] + sh : gr[i];
            cp16z(a_st + i*32*(KST*2) + st*SST, In + (size_t)rr*CH + ci0 + koff, v);
        }
#pragma unroll
        for (int i = 0; i < 4; i++)
            cp16u(b_st + i*32*(KST*2) + st*SST,
                  Wl + ((size_t)kk*CH + n0 + lr + i*32)*CH + ci0 + koff);
        cpcommit();
    };
    const int nch = 20;
    const int cb = kh * 20;
    load(0, cb + 0);
    load(1, cb + 1);
    for (int ch = 0; ch < nch; ch++) {
        cpwait<1>();
        __syncthreads();
        const uint32_t sb = base + (ch & 1) * SST;
#pragma unroll
        for (int ks = 0; ks < 4; ks++) {
            uint32_t af[4][4], bfr[2][4];
#pragma unroll
            for (int mf = 0; mf < 4; mf++)
                ldsm4(af[mf], sb + a_off + mf*16*KST*2 + ks*32);
            ldsm4(bfr[0], sb + b_off + ks*32);
            ldsm4(bfr[1], sb + b_off + 16*KST*2 + ks*32);
#pragma unroll
            for (int mf = 0; mf < 4; mf++)
#pragma unroll
                for (int nf = 0; nf < 4; nf++)
                    mma16(acc[mf][nf], af[mf], &bfr[nf>>1][(nf&1)*2]);
        }
        __syncthreads();
        if (ch + 2 < nch) load(ch & 1, cb + ch + 2);
    }
#pragma unroll
    for (int mf = 0; mf < 4; mf++) {
#pragma unroll
        for (int half = 0; half < 2; half++) {
            int r = m0 + wm*64 + mf*16 + (lane>>2) + half*8;
#pragma unroll
            for (int nf = 0; nf < 4; nf++) {
                int c = n0 + wn*32 + nf*8 + (lane&3)*2;
                float2 f = {acc[mf][nf][half*2], acc[mf][nf][half*2+1]};
                *(float2*)(Out + (size_t)r*CH + c) = f;
            }
        }
    }
}

// ======== small GEMM for xdbc (BNT=64, 128 thr), z = dir*2 + kh split-K ========
__global__ __launch_bounds__(128, 2)
void gemm_xd(const bf* __restrict__ A, const bf* __restrict__ Wt,
             float* __restrict__ Out, int K) {
    constexpr int SST = 192 * KST * 2;
    extern __shared__ char smem[];
    const int t = threadIdx.x, lane = t & 31, warp = t >> 5;
    const int wm = warp;               // 4 warps along M, warp tile 32x64
    const int m0 = blockIdx.y * 128;
    const int zz = blockIdx.z;
    const int dir = zz >> 1;
    A  += (size_t)dir * BL * DI + (size_t)(zz & 1) * K;
    Wt += (size_t)dir * 64 * DI + (size_t)(zz & 1) * K;
    Out += (size_t)zz * BL * 64;

    float acc[2][8][4];
#pragma unroll
    for (int i = 0; i < 2; i++)
#pragma unroll
        for (int j = 0; j < 8; j++)
#pragma unroll
            for (int q = 0; q < 4; q++) acc[i][j][q] = 0.0f;

    const int lr   = t >> 3;
    const int koff = (t & 7) * 8;
    const uint32_t base = (uint32_t)__cvta_generic_to_shared(smem);
    const uint32_t a_st = base + lr * (KST*2) + koff*2;
    const uint32_t b_st = base + 128*(KST*2) + lr * (KST*2) + koff*2;
    const uint32_t a_off = ((wm*32 + ((lane>>3)&1)*8 + (lane&7)) * KST + (lane>>4)*8) * 2;
    const uint32_t b_off = (128*KST + (((lane>>4)&1)*8 + (lane&7)) * KST
                            + ((lane>>3)&1)*8) * 2;

    auto load = [&](int st, int k0) {
#pragma unroll
        for (int i = 0; i < 8; i++)
            cp16u(a_st + i*16*(KST*2) + st*SST,
                  A + (size_t)(m0 + lr + 16*i)*DI + k0 + koff);
#pragma unroll
        for (int i = 0; i < 4; i++)
            cp16u(b_st + i*16*(KST*2) + st*SST,
                  Wt + (size_t)(lr + i*16)*DI + k0 + koff);
        cpcommit();
    };
    load(0, 0);
    load(1, BK);
    const int nch = K >> 6;
    for (int ch = 0; ch < nch; ch++) {
        cpwait<1>();
        __syncthreads();
        const uint32_t sb = base + (ch & 1) * SST;
#pragma unroll
        for (int ks = 0; ks < 4; ks++) {
            uint32_t af[2][4], bfr[4][4];
#pragma unroll
            for (int mf = 0; mf < 2; mf++)
                ldsm4(af[mf], sb + a_off + mf*16*KST*2 + ks*32);
#pragma unroll
            for (int g = 0; g < 4; g++)
                ldsm4(bfr[g], sb + b_off + g*16*KST*2 + ks*32);
#pragma unroll
            for (int mf = 0; mf < 2; mf++)
#pragma unroll
                for (int nf = 0; nf < 8; nf++)
                    mma16(acc[mf][nf], af[mf], &bfr[nf>>1][(nf&1)*2]);
        }
        __syncthreads();
        if (ch + 2 < nch) load(ch & 1, (ch + 2) * BK);
    }
#pragma unroll
    for (int mf = 0; mf < 2; mf++) {
#pragma unroll
        for (int half = 0; half < 2; half++) {
            int r = m0 + wm*32 + mf*16 + (lane>>2) + half*8;
#pragma unroll
            for (int nf = 0; nf < 8; nf++) {
                int c = nf*8 + (lane&3)*2;
                float2 f = {acc[mf][nf][half*2], acc[mf][nf][half*2+1]};
                *(float2*)(Out + (size_t)r*64 + c) = f;
            }
        }
    }
}

// ---------------- channel LayerNorm + LeakyReLU + mask (sums split-K + bias) ----------------
__global__ void ln_k(const float* __restrict__ In, const float* __restrict__ cb,
                     const float* __restrict__ gamma, const float* __restrict__ beta,
                     const unsigned char* __restrict__ m, bf* __restrict__ Out) {
    int row = blockIdx.x;
    int t = threadIdx.x;   // 128
    float v[4];
    float s = 0.0f;
#pragma unroll
    for (int i = 0; i < 4; i++) {
        int c = t + i * 128;
        v[i] = In[(size_t)row * CH + c] + In[(size_t)BL*CH + (size_t)row * CH + c] + cb[c];
        s += v[i];
    }
    __shared__ float sm[4];
    for (int o = 16; o > 0; o >>= 1) s += __shfl_xor_sync(~0u, s, o);
    if ((t & 31) == 0) sm[t >> 5] = s;
    __syncthreads();
    float mean = (sm[0] + sm[1] + sm[2] + sm[3]) * (1.0f / CH);
    __syncthreads();
    float s2 = 0.0f;
#pragma unroll
    for (int i = 0; i < 4; i++) { float d = v[i] - mean; s2 += d * d; }
    for (int o = 16; o > 0; o >>= 1) s2 += __shfl_xor_sync(~0u, s2, o);
    if ((t & 31) == 0) sm[t >> 5] = s2;
    __syncthreads();
    float var = (sm[0] + sm[1] + sm[2] + sm[3]) * (1.0f / CH);
    float rstd = rsqrtf(var + 1e-5f);
    unsigned char mm = m[row];
#pragma unroll
    for (int i = 0; i < 4; i++) {
        int c = t + i * 128;
        float h = (v[i] - mean) * rstd * gamma[c] + beta[c];
        h = (h > 0.0f) ? h : 0.2f * h;
        if (mm) h = 0.0f;
        Out[(size_t)row * CH + c] = __float2bfloat16(h);
    }
}

// ---------------- final combine: out = p0 + p1 + bias, masked ----------------
__global__ void comb_k(const float* __restrict__ p, const float* __restrict__ bias,
                       const unsigned char* __restrict__ m, float* __restrict__ out) {
    int i = blockIdx.x * 256 + threadIdx.x;
    if (i >= BL * CH / 4) return;
    int r = i >> 7;
    int c4 = i & 127;
    float4 a = ((const float4*)p)[i];
    float4 b = ((const float4*)p)[BL*CH/4 + i];
    float4 bb = ((const float4*)bias)[c4];
    float4 v;
    v.x = a.x + b.x + bb.x; v.y = a.y + b.y + bb.y;
    v.z = a.z + b.z + bb.z; v.w = a.w + b.w + bb.w;
    if (m[r]) { v.x = 0.0f; v.y = 0.0f; v.z = 0.0f; v.w = 0.0f; }
    ((float4*)out)[i] = v;
}

// ---------------- causal depthwise conv + SiLU, 2 timesteps/thread ----------------
__global__ void dwconv_k(const bf* __restrict__ xz,
                         const float* __restrict__ cwf, const float* __restrict__ cbf,
                         const float* __restrict__ cwb, const float* __restrict__ cbb,
                         bf* __restrict__ out) {
    int idx = blockIdx.x * blockDim.x + threadIdx.x;
    if (idx >= BL * DI) return;                 // pairs: 2 dirs x 2M
    int dir = idx >> 21;
    int r = idx & ((1 << 21) - 1);
    int d = r & (DI - 1);
    int p = r >> 10;                            // 0..2047 = b*512 + l2
    int l2 = p & 511, b = p >> 9;
    int l = l2 * 2;
    int row = b * SEQL + l;
    const bf* xzd = xz + ((size_t)dir << 23);
    const float* cw = dir ? cwb : cwf;
    float cb = (dir ? cbb : cbf)[d];
    float w0 = cw[d*4], w1 = cw[d*4+1], w2 = cw[d*4+2], w3 = cw[d*4+3];
    float tap[5];
#pragma unroll
    for (int j = 0; j < 5; j++) {
        int lp = l - 3 + j;
        tap[j] = (lp >= 0 && lp < SEQL)
               ? __bfloat162float(xzd[(size_t)(b*SEQL + lp)*XZW + d]) : 0.0f;
    }
    float a0 = cb + w0*tap[0] + w1*tap[1] + w2*tap[2] + w3*tap[3];
    float a1 = cb + w0*tap[1] + w1*tap[2] + w2*tap[3] + w3*tap[4];
    bf* ob = out + ((size_t)dir << 22);
    ob[(size_t)row*DI + d]       = __float2bfloat16(siluf(a0));
    ob[(size_t)(row+1)*DI + d]   = __float2bfloat16(siluf(a1));
}

// -------- delta = softplus(xdbc @ dt_w.T + dt_b); sums split-K partials;
// -------- blockIdx.x==0 also writes combined B/C columns for the scan --------
__global__ __launch_bounds__(256)
void dt_k(const float* __restrict__ xdbc,
          const float* __restrict__ wf, const float* __restrict__ dbf,
          const float* __restrict__ wb, const float* __restrict__ dbb,
          float* __restrict__ delta, float* __restrict__ xsum) {
    int dir = blockIdx.z;
    const float* x0 = xdbc + (size_t)dir * 2 * BL * 64;
    const float* x1 = x0 + (size_t)BL * 64;
    delta += (size_t)dir * BL * DI;
    xsum  += (size_t)dir * BL * 64;
    const float* dt_w = dir ? wb : wf;
    const float* dt_b = dir ? dbb : dbf;
    __shared__ float xs[32][32];
    int t = threadIdx.x;
    int d0 = blockIdx.x * 256, m0 = blockIdx.y * 32;
#pragma unroll
    for (int i = 0; i < 4; i++) {
        int idx = t + i * 256;
        int rr = idx >> 5, c = idx & 31;
        size_t off = (size_t)(m0 + rr) * 64 + c;
        xs[rr][c] = x0[off] + x1[off];
    }
    if (blockIdx.x == 0) {
#pragma unroll
        for (int i = 0; i < 4; i++) {
            int idx = t + i * 256;
            int rr = idx >> 5, c = 32 + (idx & 31);
            size_t off = (size_t)(m0 + rr) * 64 + c;
            xsum[off] = x0[off] + x1[off];
        }
    }
    int d = d0 + t;
    float4 wr[8];
#pragma unroll
    for (int j = 0; j < 8; j++) wr[j] = *(const float4*)(dt_w + (size_t)d*DTR + j*4);
    float b = dt_b[d];
    __syncthreads();
#pragma unroll 4
    for (int row = 0; row < 32; row++) {
        float acc = b;
#pragma unroll
        for (int j = 0; j < 8; j++) {
            float4 x4 = *(const float4*)&xs[row][j*4];
            acc = fmaf(wr[j].x, x4.x, acc);
            acc = fmaf(wr[j].y, x4.y, acc);
            acc = fmaf(wr[j].z, x4.z, acc);
            acc = fmaf(wr[j].w, x4.w, acc);
        }
        delta[(size_t)(m0 + row) * DI + d] = softplusf(acc);
    }
}

// ======== selective scan + gate: 4 threads per d, 4 states, depth-4 prefetch ========
__global__ __launch_bounds__(128)
void scan_k(const float* __restrict__ delta, const bf* __restrict__ u,
            const float* __restrict__ xsum, const bf* __restrict__ xz,
            const float* __restrict__ Af, const float* __restrict__ Df,
            const float* __restrict__ Ab, const float* __restrict__ Db,
            bf* __restrict__ y) {
    int dir = blockIdx.z;
    delta += (size_t)dir * BL * DI;
    u     += (size_t)dir * BL * DI;
    xsum  += (size_t)dir * BL * 64;
    xz    += (size_t)dir * BL * XZW;
    const float* A_log = dir ? Ab : Af;
    const float* Dv    = dir ? Db : Df;
    int t = threadIdx.x;
    int q = t & 3;
    int d = blockIdx.x * 32 + (t >> 2);
    int b = blockIdx.y;

    float aa[4];
#pragma unroll
    for (int n = 0; n < 4; n++)
        aa[n] = -__expf(A_log[d * DS + q*4 + n]) * 1.4426950408889634f;
    float Dd = Dv[d];
    float h[4];
#pragma unroll
    for (int n = 0; n < 4; n++) h[n] = 0.0f;

    int base = b * SEQL;
    const float* pd = delta + (size_t)base * DI + d;
    const bf*    pu = u     + (size_t)base * DI + d;
    const bf*    pz = xz    + (size_t)base * XZW + DI + d;
    const float* pb = xsum  + (size_t)base * 64 + 32 + q*4;
    bf*          py = y + (size_t)base * 2048 + dir*1024 + d;

    // depth-4 ring (static slots via unrolled loop)
    float rde[4], ruu[4], rz[4];
    float4 rB[4], rC[4];
#pragma unroll
    for (int s = 0; s < 4; s++) {
        rde[s] = pd[(size_t)s*DI];
        ruu[s] = __bfloat162float(pu[(size_t)s*DI]);
        rz[s]  = __bfloat162float(pz[(size_t)s*XZW]);
        rB[s]  = *(const float4*)(pb + s*64);
        rC[s]  = *(const float4*)(pb + s*64 + 16);
    }
    for (int l4 = 0; l4 < SEQL; l4 += 4) {
#pragma unroll
        for (int s = 0; s < 4; s++) {
            int l = l4 + s;
            float de0 = rde[s], uu0 = ruu[s], z0 = rz[s];
            float4 B0 = rB[s], C0 = rC[s];
            // prefetch l+4 into this slot
            if (l + 4 < SEQL) {
                rde[s] = pd[(size_t)4*DI];
                ruu[s] = __bfloat162float(pu[(size_t)4*DI]);
                rz[s]  = __bfloat162float(pz[(size_t)4*XZW]);
                rB[s]  = *(const float4*)(pb + 4*64);
                rC[s]  = *(const float4*)(pb + 4*64 + 16);
            }
            float du = de0 * uu0;
            const float* Bf = (const float*)&B0;
            const float* Cf = (const float*)&C0;
            float a0 = 0.0f, a1 = 0.0f;
#pragma unroll
            for (int n = 0; n < 4; n++) {
                float dA = exp2f(de0 * aa[n]);
                h[n] = fmaf(dA, h[n], du * Bf[n]);
                float tt = h[n] * Cf[n];
                if (n & 1) a1 += tt; else a0 += tt;
            }
            float part = a0 + a1;
            part += __shfl_xor_sync(0xffffffffu, part, 1);
            part += __shfl_xor_sync(0xffffffffu, part, 2);
            if (q == 0) {
                float yy = part + uu0 * Dd;
                float sg = z0 / (1.0f + __expf(-z0));
                py[0] = __float2bfloat16(yy * sg);
            }
            pd += DI; pu += DI; pz += XZW; pb += 64; py += 2048;
        }
    }
}

// ---------------- launch ----------------
template <typename T>
static T* symp(const void* sym) {
    void* p = nullptr;
    cudaGetSymbolAddress(&p, sym);
    return (T*)p;
}

#define SMEM2_128 (2 * 256 * KST * 2)   // 73728
#define SMEM2_64  (2 * 192 * KST * 2)   // 55296

extern "C" void kernel_launch(void* const* d_in, const int* in_sizes, int n_in,
                              void* d_out, int out_size) {
    const int*           x      = (const int*)d_in[0];
    const unsigned char* m      = (const unsigned char*)d_in[2];
    const float*         emb    = (const float*)d_in[3];
    const float*         conv_w = (const float*)d_in[4];
    const float*         conv_b = (const float*)d_in[5];
    const float*         ln_g   = (const float*)d_in[6];
    const float*         ln_b   = (const float*)d_in[7];
    const float*         proj_b = (const float*)d_in[9];
    float* out = (float*)d_out;

    bf*    h    = symp<bf>(g_h);
    float* tmp  = symp<float>(g_tmp);
    bf*    xz   = symp<bf>(g_xz);
    bf*    u    = symp<bf>(g_u);
    float* dl   = symp<float>(g_delta);
    float* xdbc = symp<float>(g_xdbc);
    float* xs   = symp<float>(g_xs);
    bf*    y    = symp<bf>(g_y);
    bf*    cwt  = symp<bf>(g_cwt);
    bf*    inw  = symp<bf>(g_inw);
    bf*    xw   = symp<bf>(g_xw);
    bf*    owT  = symp<bf>(g_owT);
    bf*    prw  = symp<bf>(g_projw);
    bf*    wfu  = symp<bf>(g_wfuse);

    cudaFuncSetAttribute(conv256, cudaFuncAttributeMaxDynamicSharedMemorySize, SMEM2_128);
    cudaFuncSetAttribute((const void*)gemm256<0>, cudaFuncAttributeMaxDynamicSharedMemorySize, SMEM2_128);
    cudaFuncSetAttribute((const void*)gemm256<1>, cudaFuncAttributeMaxDynamicSharedMemorySize, SMEM2_128);
    cudaFuncSetAttribute(gemm_xd, cudaFuncAttributeMaxDynamicSharedMemorySize, SMEM2_64);

    // 1: merged weight conversion
    {
        CvtP p;
        p.s[0] = (const float*)d_in[10];  p.d[0] = inw;
        p.s[1] = (const float*)d_in[19];  p.d[1] = inw + (size_t)XZW*CH;
        p.s[2] = (const float*)d_in[13];  p.d[2] = xw;
        p.s[3] = (const float*)d_in[22];  p.d[3] = xw + (size_t)64*DI;
        p.s[4] = (const float*)d_in[8];   p.d[4] = prw;
        p.owf  = (const float*)d_in[18];
        p.owb  = (const float*)d_in[27];
        cvt_all<<<3*CH + 256 + 2768, 256>>>(conv_w, p);
    }
    // 2: Wfuse[c][dir*1024+e] = sum_k projw[c][dir*CH+k] * owT[dir][e][k]
    gemm256<0><<<dim3(DI/128, CH/128, 2), 256, SMEM2_128>>>(
        prw, owT, wfu, CH, 2*CH, CH, 2048, 0,
        (size_t)CH, (size_t)DI*CH, (size_t)DI);
    // 3: embedding
    embed_k<<<(BL*CH + 255)/256, 256>>>(x, emb, h);

    // 4-9: conv stack (launch #6 = conv layer 1 for ncu capture)
    for (int layer = 0; layer < 3; layer++) {
        conv256<<<dim3(CH/128, BL/128, 2), 256, SMEM2_128>>>(
            h, cwt + (size_t)layer*KW*CH*CH, tmp);
        ln_k<<<BL, 128>>>(tmp, conv_b + layer*CH, ln_g + layer*CH, ln_b + layer*CH, m, h);
    }

    const float* mcwf = (const float*)d_in[11];
    const float* mcbf = (const float*)d_in[12];
    const float* mcwb = (const float*)d_in[20];
    const float* mcbb = (const float*)d_in[21];
    const float* dtwf = (const float*)d_in[14];
    const float* dtbf = (const float*)d_in[15];
    const float* dtwb = (const float*)d_in[23];
    const float* dtbb = (const float*)d_in[24];
    const float* Alf  = (const float*)d_in[16];
    const float* Dvf  = (const float*)d_in[17];
    const float* Alb  = (const float*)d_in[25];
    const float* Dvb  = (const float*)d_in[26];

    // in-proj: xz[dir] = h(rev if dir) @ inw[dir]^T
    gemm256<0><<<dim3(XZW/128, BL/128, 2), 256, SMEM2_128>>>(
        h, inw, xz, CH, CH, CH, XZW, 1,
        0, (size_t)XZW*CH, (size_t)BL*XZW);
    // depthwise conv + silu (2 timesteps per thread)
    dwconv_k<<<(BL*DI + 255)/256, 256>>>(xz, mcwf, mcbf, mcwb, mcbb, u);
    // xdbc partials = u @ xw^T, split-K=2 (z = dir*2 + kh)
    gemm_xd<<<dim3(1, BL/128, 4), 128, SMEM2_64>>>(u, xw, xdbc, 512);
    // delta (+ B/C combine into xs)
    dt_k<<<dim3(DI/256, BL/32, 2), 256>>>(xdbc, dtwf, dtbf, dtwb, dtbb, dl, xs);
    // selective scan + gate -> y [row][dir*1024+d]
    scan_k<<<dim3(DI/32, BATCH, 2), 128>>>(dl, u, xs, xz, Alf, Dvf, Alb, Dvb, y);
    // fused out-proj + final projection, split-K=2: partials into tmp
    gemm256<1><<<dim3(CH/128, BL/128, 2), 256, SMEM2_128>>>(
        y, wfu, tmp, 1024, 2048, 2048, CH, 0,
        (size_t)1024, (size_t)1024, (size_t)BL*CH);
    // combine partials + bias + mask -> out
    comb_k<<<(BL*CH/4 + 255)/256, 256>>>(tmp, proj_b, m, out);
}

// round 16
// speedup vs baseline: 1.6640x; 1.6640x over previous
#include <cuda_runtime.h>
#include <cuda_bf16.h>
#include <cstdint>

#define BATCH 4
#define SEQL  1024
#define CH    512
#define KW    5
#define DI    1024
#define DS    16
#define DTR   32
#define BL    (BATCH*SEQL)
#define XZW   (2*DI)

#define BK  64
#define KST 72   // BK + 8 pad (bf16 elems), 144B row stride

typedef __nv_bfloat16 bf;

// ---------------- scratch ----------------
__device__ bf    g_h[BL*CH];
__device__ float g_tmp[2ull*BL*CH];
__device__ bf    g_xz[2ull*BL*XZW];
__device__ bf    g_u[2ull*BL*DI];
__device__ float g_delta[2ull*BL*DI];
__device__ float g_xdbc[4ull*BL*64];
__device__ float g_xs[2ull*BL*64];
__device__ bf    g_y[(size_t)BL*2048];
__device__ bf    g_cwt[3ull*KW*CH*CH];
__device__ bf    g_inw[2ull*XZW*CH];
__device__ bf    g_xw[2ull*64*DI];
__device__ bf    g_owT[2ull*DI*CH];
__device__ bf    g_projw[(size_t)CH*2*CH];
__device__ bf    g_wfuse[(size_t)CH*2048];

// ---------------- helpers ----------------
__device__ __forceinline__ float siluf(float x) { return x / (1.0f + __expf(-x)); }
__device__ __forceinline__ float softplusf(float x) {
    return fmaxf(x, 0.0f) + log1pf(__expf(-fabsf(x)));
}
__device__ __forceinline__ void cp16u(uint32_t d, const void* s) {
    asm volatile("cp.async.cg.shared.global [%0], [%1], 16;" :: "r"(d), "l"(s));
}
__device__ __forceinline__ void cp16z(uint32_t d, const void* s, int valid) {
    int sz = valid ? 16 : 0;
    asm volatile("cp.async.cg.shared.global [%0], [%1], 16, %2;" :: "r"(d), "l"(s), "r"(sz));
}
__device__ __forceinline__ void cpcommit() { asm volatile("cp.async.commit_group;"); }
template<int N> __device__ __forceinline__ void cpwait() {
    asm volatile("cp.async.wait_group %0;" :: "n"(N));
}
__device__ __forceinline__ void ldsm4(uint32_t* r, uint32_t a) {
    asm volatile("ldmatrix.sync.aligned.m8n8.x4.shared.b16 {%0,%1,%2,%3}, [%4];"
        : "=r"(r[0]), "=r"(r[1]), "=r"(r[2]), "=r"(r[3]) : "r"(a));
}
__device__ __forceinline__ void mma16(float* d, const uint32_t* a, const uint32_t* b) {
    asm volatile(
        "mma.sync.aligned.m16n8k16.row.col.f32.bf16.bf16.f32 "
        "{%0,%1,%2,%3}, {%4,%5,%6,%7}, {%8,%9}, {%0,%1,%2,%3};"
        : "+f"(d[0]), "+f"(d[1]), "+f"(d[2]), "+f"(d[3])
        : "r"(a[0]), "r"(a[1]), "r"(a[2]), "r"(a[3]), "r"(b[0]), "r"(b[1]));
}

// ---------------- merged weight conversion ----------------
struct CvtP { const float* s[5]; bf* d[5]; const float* owf; const float* owb; };
__global__ void cvt_all(const float* __restrict__ conv_w, CvtP p) {
    __shared__ float s[64*65];
    int bx = blockIdx.x;
    if (bx < 3*CH) {
        int co = bx & 511, layer = bx >> 9;
        const float* src = conv_w + (size_t)bx * (CH*KW);
        for (int i = threadIdx.x; i < CH*KW; i += 256) s[i] = src[i];
        __syncthreads();
        bf* dst = g_cwt + (size_t)layer * KW * CH * CH;
        for (int i = threadIdx.x; i < CH*KW; i += 256) {
            int k = i >> 9, ci = i & 511;
            dst[(size_t)k*CH*CH + (size_t)co*CH + ci] = __float2bfloat16(s[ci*KW + k]);
        }
    } else if (bx < 3*CH + 256) {
        int idx = bx - 3*CH;
        int dir = idx >> 7;
        int te = (idx & 127) >> 3, tk = idx & 7;
        const float* ow = dir ? p.owb : p.owf;
        for (int i = threadIdx.x; i < 4096; i += 256) {
            int kk = i >> 6, ee = i & 63;
            s[kk*65 + ee] = ow[(size_t)(tk*64 + kk)*DI + te*64 + ee];
        }
        __syncthreads();
        bf* dst = g_owT + (size_t)dir*DI*CH;
        for (int i = threadIdx.x; i < 4096; i += 256) {
            int ee = i >> 6, kk = i & 63;
            dst[(size_t)(te*64 + ee)*CH + tk*64 + kk] = __float2bfloat16(s[kk*65 + ee]);
        }
    } else {
        const int sz[5] = {262144, 262144, 16384, 16384, 131072};
        int i = (bx - 3*CH - 256) * 256 + threadIdx.x;
        int seg = 0;
#pragma unroll
        for (int q = 0; q < 5; q++) {
            if (seg == q && i >= sz[q]) { i -= sz[q]; seg = q + 1; }
        }
        if (seg >= 5) return;
        float4 v = ((const float4*)p.s[seg])[i];
        __nv_bfloat162* o = (__nv_bfloat162*)p.d[seg];
        o[i*2]   = __floats2bfloat162_rn(v.x, v.y);
        o[i*2+1] = __floats2bfloat162_rn(v.z, v.w);
    }
}

// ---------------- embedding ----------------
__global__ void embed_k(const int* __restrict__ x, const float* __restrict__ emb,
                        bf* __restrict__ out) {
    int i = blockIdx.x * blockDim.x + threadIdx.x;
    if (i >= BL * CH) return;
    int row = i >> 9, c = i & (CH - 1);
    out[i] = __float2bfloat16(emb[x[row] * CH + c]);
}

// ======== bf16 MMA GEMM, 128x128 tile, 8 warps (64x32 warp tile), 2-stage ========
template <int EPI>
__global__ __launch_bounds__(256, 2)
void gemm256(const bf* __restrict__ A, const bf* __restrict__ Wt,
             void* __restrict__ OutV,
             int K, int lda, int ldw, int ldo, int revz,
             size_t az, size_t wz, size_t oz) {
    constexpr int SST = 256 * KST * 2;
    extern __shared__ char smem[];

    const int t = threadIdx.x, lane = t & 31, warp = t >> 5;
    const int wm = warp >> 2, wn = warp & 3;
    const int m0 = blockIdx.y * 128, n0 = blockIdx.x * 128;
    const int zz = blockIdx.z;
    A  += (size_t)zz * az;
    Wt += (size_t)zz * wz;
    const int rev = revz && zz;

    float acc[4][4][4];
#pragma unroll
    for (int i = 0; i < 4; i++)
#pragma unroll
        for (int j = 0; j < 4; j++)
#pragma unroll
            for (int q = 0; q < 4; q++) acc[i][j][q] = 0.0f;

    const int lr   = t >> 3;
    const int koff = (t & 7) * 8;
    int ga[4];
#pragma unroll
    for (int i = 0; i < 4; i++) {
        int r = m0 + lr + 32*i;
        ga[i] = rev ? ((r & ~(SEQL-1)) + (SEQL-1) - (r & (SEQL-1))) : r;
    }
    const uint32_t base = (uint32_t)__cvta_generic_to_shared(smem);
    const uint32_t a_st = base + lr * (KST*2) + koff*2;
    const uint32_t b_st = base + 128*(KST*2) + lr * (KST*2) + koff*2;
    const uint32_t a_off = ((wm*64 + ((lane>>3)&1)*8 + (lane&7)) * KST + (lane>>4)*8) * 2;
    const uint32_t b_off = (128*KST + (wn*32 + ((lane>>4)&1)*8 + (lane&7)) * KST
                            + ((lane>>3)&1)*8) * 2;

    auto load = [&](int st, int k0) {
#pragma unroll
        for (int i = 0; i < 4; i++)
            cp16u(a_st + i*32*(KST*2) + st*SST, A + (size_t)ga[i]*lda + k0 + koff);
#pragma unroll
        for (int i = 0; i < 4; i++)
            cp16u(b_st + i*32*(KST*2) + st*SST,
                  Wt + (size_t)(n0 + lr + i*32)*ldw + k0 + koff);
        cpcommit();
    };
    load(0, 0);
    load(1, BK);
    const int nch = K >> 6;
    for (int ch = 0; ch < nch; ch++) {
        cpwait<1>();
        __syncthreads();
        const uint32_t sb = base + (ch & 1) * SST;
#pragma unroll
        for (int ks = 0; ks < 4; ks++) {
            uint32_t af[4][4], bfr[2][4];
#pragma unroll
            for (int mf = 0; mf < 4; mf++)
                ldsm4(af[mf], sb + a_off + mf*16*KST*2 + ks*32);
            ldsm4(bfr[0], sb + b_off + ks*32);
            ldsm4(bfr[1], sb + b_off + 16*KST*2 + ks*32);
#pragma unroll
            for (int mf = 0; mf < 4; mf++)
#pragma unroll
                for (int nf = 0; nf < 4; nf++)
                    mma16(acc[mf][nf], af[mf], &bfr[nf>>1][(nf&1)*2]);
        }
        __syncthreads();
        if (ch + 2 < nch) load(ch & 1, (ch + 2) * BK);
    }
#pragma unroll
    for (int mf = 0; mf < 4; mf++) {
#pragma unroll
        for (int half = 0; half < 2; half++) {
            int r = m0 + wm*64 + mf*16 + (lane>>2) + half*8;
#pragma unroll
            for (int nf = 0; nf < 4; nf++) {
                int c = n0 + wn*32 + nf*8 + (lane&3)*2;
                float v0 = acc[mf][nf][half*2], v1 = acc[mf][nf][half*2+1];
                if (EPI == 0) {
                    bf* Ob = (bf*)OutV + (size_t)zz*oz;
                    *(__nv_bfloat162*)(Ob + (size_t)r*ldo + c) =
                        __floats2bfloat162_rn(v0, v1);
                } else {
                    float* Of = (float*)OutV + (size_t)zz*oz;
                    float2 f = {v0, v1};
                    *(float2*)(Of + (size_t)r*ldo + c) = f;
                }
            }
        }
    }
}

// ======== conv1d GEMM, 256 thr, 8 warps 64x32, split-K via blockIdx.z ========
__global__ __launch_bounds__(256, 2)
void conv256(const bf* __restrict__ In, const bf* __restrict__ Wl,
             float* __restrict__ Out) {
    constexpr int SST = 256 * KST * 2;
    extern __shared__ char smem[];
    const int t = threadIdx.x, lane = t & 31, warp = t >> 5;
    const int wm = warp >> 2, wn = warp & 3;
    const int m0 = blockIdx.y * 128, n0 = blockIdx.x * 128;
    const int kh = blockIdx.z;
    Out += (size_t)kh * BL * CH;

    float acc[4][4][4];
#pragma unroll
    for (int i = 0; i < 4; i++)
#pragma unroll
        for (int j = 0; j < 4; j++)
#pragma unroll
            for (int q = 0; q < 4; q++) acc[i][j][q] = 0.0f;

    const int lr   = t >> 3;
    const int koff = (t & 7) * 8;
    int gr[4], lc[4];
#pragma unroll
    for (int i = 0; i < 4; i++) {
        gr[i] = m0 + lr + 32*i;
        lc[i] = gr[i] & (SEQL - 1);
    }
    const uint32_t base = (uint32_t)__cvta_generic_to_shared(smem);
    const uint32_t a_st = base + lr * (KST*2) + koff*2;
    const uint32_t b_st = base + 128*(KST*2) + lr * (KST*2) + koff*2;
    const uint32_t a_off = ((wm*64 + ((lane>>3)&1)*8 + (lane&7)) * KST + (lane>>4)*8) * 2;
    const uint32_t b_off = (128*KST + (wn*32 + ((lane>>4)&1)*8 + (lane&7)) * KST
                            + ((lane>>3)&1)*8) * 2;

    auto load = [&](int st, int chg) {
        int kk = chg >> 3, ci0 = (chg & 7) << 6;
        int sh = kk - 2;
#pragma unroll
        for (int i = 0; i < 4; i++) {
            int v = (unsigned)(lc[i] + sh) < (unsigned)SEQL;
            int rr = v ? gr[i] + sh : gr[i];
            cp16z(a_st + i*32*(KST*2) + st*SST, In + (size_t)rr*CH + ci0 + koff, v);
        }
#pragma unroll
        for (int i = 0; i < 4; i++)
            cp16u(b_st + i*32*(KST*2) + st*SST,
                  Wl + ((size_t)kk*CH + n0 + lr + i*32)*CH + ci0 + koff);
        cpcommit();
    };
    const int nch = 20;
    const int cb = kh * 20;
    load(0, cb + 0);
    load(1, cb + 1);
    for (int ch = 0; ch < nch; ch++) {
        cpwait<1>();
        __syncthreads();
        const uint32_t sb = base + (ch & 1) * SST;
#pragma unroll
        for (int ks = 0; ks < 4; ks++) {
            uint32_t af[4][4], bfr[2][4];
#pragma unroll
            for (int mf = 0; mf < 4; mf++)
                ldsm4(af[mf], sb + a_off + mf*16*KST*2 + ks*32);
            ldsm4(bfr[0], sb + b_off + ks*32);
            ldsm4(bfr[1], sb + b_off + 16*KST*2 + ks*32);
#pragma unroll
            for (int mf = 0; mf < 4; mf++)
#pragma unroll
                for (int nf = 0; nf < 4; nf++)
                    mma16(acc[mf][nf], af[mf], &bfr[nf>>1][(nf&1)*2]);
        }
        __syncthreads();
        if (ch + 2 < nch) load(ch & 1, cb + ch + 2);
    }
#pragma unroll
    for (int mf = 0; mf < 4; mf++) {
#pragma unroll
        for (int half = 0; half < 2; half++) {
            int r = m0 + wm*64 + mf*16 + (lane>>2) + half*8;
#pragma unroll
            for (int nf = 0; nf < 4; nf++) {
                int c = n0 + wn*32 + nf*8 + (lane&3)*2;
                float2 f = {acc[mf][nf][half*2], acc[mf][nf][half*2+1]};
                *(float2*)(Out + (size_t)r*CH + c) = f;
            }
        }
    }
}

// ======== small GEMM for xdbc (BNT=64, 128 thr), z = dir*2 + kh split-K ========
__global__ __launch_bounds__(128, 2)
void gemm_xd(const bf* __restrict__ A, const bf* __restrict__ Wt,
             float* __restrict__ Out, int K) {
    constexpr int SST = 192 * KST * 2;
    extern __shared__ char smem[];
    const int t = threadIdx.x, lane = t & 31, warp = t >> 5;
    const int wm = warp;
    const int m0 = blockIdx.y * 128;
    const int zz = blockIdx.z;
    const int dir = zz >> 1;
    A  += (size_t)dir * BL * DI + (size_t)(zz & 1) * K;
    Wt += (size_t)dir * 64 * DI + (size_t)(zz & 1) * K;
    Out += (size_t)zz * BL * 64;

    float acc[2][8][4];
#pragma unroll
    for (int i = 0; i < 2; i++)
#pragma unroll
        for (int j = 0; j < 8; j++)
#pragma unroll
            for (int q = 0; q < 4; q++) acc[i][j][q] = 0.0f;

    const int lr   = t >> 3;
    const int koff = (t & 7) * 8;
    const uint32_t base = (uint32_t)__cvta_generic_to_shared(smem);
    const uint32_t a_st = base + lr * (KST*2) + koff*2;
    const uint32_t b_st = base + 128*(KST*2) + lr * (KST*2) + koff*2;
    const uint32_t a_off = ((wm*32 + ((lane>>3)&1)*8 + (lane&7)) * KST + (lane>>4)*8) * 2;
    const uint32_t b_off = (128*KST + (((lane>>4)&1)*8 + (lane&7)) * KST
                            + ((lane>>3)&1)*8) * 2;

    auto load = [&](int st, int k0) {
#pragma unroll
        for (int i = 0; i < 8; i++)
            cp16u(a_st + i*16*(KST*2) + st*SST,
                  A + (size_t)(m0 + lr + 16*i)*DI + k0 + koff);
#pragma unroll
        for (int i = 0; i < 4; i++)
            cp16u(b_st + i*16*(KST*2) + st*SST,
                  Wt + (size_t)(lr + i*16)*DI + k0 + koff);
        cpcommit();
    };
    load(0, 0);
    load(1, BK);
    const int nch = K >> 6;
    for (int ch = 0; ch < nch; ch++) {
        cpwait<1>();
        __syncthreads();
        const uint32_t sb = base + (ch & 1) * SST;
#pragma unroll
        for (int ks = 0; ks < 4; ks++) {
            uint32_t af[2][4], bfr[4][4];
#pragma unroll
            for (int mf = 0; mf < 2; mf++)
                ldsm4(af[mf], sb + a_off + mf*16*KST*2 + ks*32);
#pragma unroll
            for (int g = 0; g < 4; g++)
                ldsm4(bfr[g], sb + b_off + g*16*KST*2 + ks*32);
#pragma unroll
            for (int mf = 0; mf < 2; mf++)
#pragma unroll
                for (int nf = 0; nf < 8; nf++)
                    mma16(acc[mf][nf], af[mf], &bfr[nf>>1][(nf&1)*2]);
        }
        __syncthreads();
        if (ch + 2 < nch) load(ch & 1, (ch + 2) * BK);
    }
#pragma unroll
    for (int mf = 0; mf < 2; mf++) {
#pragma unroll
        for (int half = 0; half < 2; half++) {
            int r = m0 + wm*32 + mf*16 + (lane>>2) + half*8;
#pragma unroll
            for (int nf = 0; nf < 8; nf++) {
                int c = nf*8 + (lane&3)*2;
                float2 f = {acc[mf][nf][half*2], acc[mf][nf][half*2+1]};
                *(float2*)(Out + (size_t)r*64 + c) = f;
            }
        }
    }
}

// ---------------- channel LayerNorm + LeakyReLU + mask (sums split-K + bias) ----------------
__global__ void ln_k(const float* __restrict__ In, const float* __restrict__ cb,
                     const float* __restrict__ gamma, const float* __restrict__ beta,
                     const unsigned char* __restrict__ m, bf* __restrict__ Out) {
    int row = blockIdx.x;
    int t = threadIdx.x;   // 128
    float v[4];
    float s = 0.0f;
#pragma unroll
    for (int i = 0; i < 4; i++) {
        int c = t + i * 128;
        v[i] = In[(size_t)row * CH + c] + In[(size_t)BL*CH + (size_t)row * CH + c] + cb[c];
        s += v[i];
    }
    __shared__ float sm[4];
    for (int o = 16; o > 0; o >>= 1) s += __shfl_xor_sync(~0u, s, o);
    if ((t & 31) == 0) sm[t >> 5] = s;
    __syncthreads();
    float mean = (sm[0] + sm[1] + sm[2] + sm[3]) * (1.0f / CH);
    __syncthreads();
    float s2 = 0.0f;
#pragma unroll
    for (int i = 0; i < 4; i++) { float d = v[i] - mean; s2 += d * d; }
    for (int o = 16; o > 0; o >>= 1) s2 += __shfl_xor_sync(~0u, s2, o);
    if ((t & 31) == 0) sm[t >> 5] = s2;
    __syncthreads();
    float var = (sm[0] + sm[1] + sm[2] + sm[3]) * (1.0f / CH);
    float rstd = rsqrtf(var + 1e-5f);
    unsigned char mm = m[row];
#pragma unroll
    for (int i = 0; i < 4; i++) {
        int c = t + i * 128;
        float h = (v[i] - mean) * rstd * gamma[c] + beta[c];
        h = (h > 0.0f) ? h : 0.2f * h;
        if (mm) h = 0.0f;
        Out[(size_t)row * CH + c] = __float2bfloat16(h);
    }
}

// ---------------- final combine: out = p0 + p1 + bias, masked ----------------
__global__ void comb_k(const float* __restrict__ p, const float* __restrict__ bias,
                       const unsigned char* __restrict__ m, float* __restrict__ out) {
    int i = blockIdx.x * 256 + threadIdx.x;
    if (i >= BL * CH / 4) return;
    int r = i >> 7;
    int c4 = i & 127;
    float4 a = ((const float4*)p)[i];
    float4 b = ((const float4*)p)[BL*CH/4 + i];
    float4 bb = ((const float4*)bias)[c4];
    float4 v;
    v.x = a.x + b.x + bb.x; v.y = a.y + b.y + bb.y;
    v.z = a.z + b.z + bb.z; v.w = a.w + b.w + bb.w;
    if (m[r]) { v.x = 0.0f; v.y = 0.0f; v.z = 0.0f; v.w = 0.0f; }
    ((float4*)out)[i] = v;
}

// ---------------- causal depthwise conv + SiLU (both dirs) ----------------
__global__ void dwconv_k(const bf* __restrict__ xz,
                         const float* __restrict__ cwf, const float* __restrict__ cbf,
                         const float* __restrict__ cwb, const float* __restrict__ cbb,
                         bf* __restrict__ out) {
    int idx = blockIdx.x * blockDim.x + threadIdx.x;
    if (idx >= 2*BL*DI) return;
    int dir = idx >> 22;
    int r = idx & ((1 << 22) - 1);
    int d = r & (DI - 1);
    int row = r >> 10;
    int l = row & (SEQL - 1);
    const bf* xzd = xz + ((size_t)dir << 23);
    const float* cw = dir ? cwb : cwf;
    float acc = (dir ? cbb : cbf)[d];
#pragma unroll
    for (int k = 0; k < 4; k++) {
        int lp = l - 3 + k;
        if (lp >= 0)
            acc = fmaf(cw[d*4 + k], __bfloat162float(xzd[(size_t)(row - l + lp)*XZW + d]), acc);
    }
    out[((size_t)dir << 22) + r] = __float2bfloat16(siluf(acc));
}

// -------- delta = softplus(xdbc @ dt_w.T + dt_b); sums split-K partials;
// -------- blockIdx.x==0 also writes combined B/C columns for the scan --------
__global__ __launch_bounds__(256)
void dt_k(const float* __restrict__ xdbc,
          const float* __restrict__ wf, const float* __restrict__ dbf,
          const float* __restrict__ wb, const float* __restrict__ dbb,
          float* __restrict__ delta, float* __restrict__ xsum) {
    int dir = blockIdx.z;
    const float* x0 = xdbc + (size_t)dir * 2 * BL * 64;
    const float* x1 = x0 + (size_t)BL * 64;
    delta += (size_t)dir * BL * DI;
    xsum  += (size_t)dir * BL * 64;
    const float* dt_w = dir ? wb : wf;
    const float* dt_b = dir ? dbb : dbf;
    __shared__ float xs[32][32];
    int t = threadIdx.x;
    int d0 = blockIdx.x * 256, m0 = blockIdx.y * 32;
#pragma unroll
    for (int i = 0; i < 4; i++) {
        int idx = t + i * 256;
        int rr = idx >> 5, c = idx & 31;
        size_t off = (size_t)(m0 + rr) * 64 + c;
        xs[rr][c] = x0[off] + x1[off];
    }
    if (blockIdx.x == 0) {
#pragma unroll
        for (int i = 0; i < 4; i++) {
            int idx = t + i * 256;
            int rr = idx >> 5, c = 32 + (idx & 31);
            size_t off = (size_t)(m0 + rr) * 64 + c;
            xsum[off] = x0[off] + x1[off];
        }
    }
    int d = d0 + t;
    float4 wr[8];
#pragma unroll
    for (int j = 0; j < 8; j++) wr[j] = *(const float4*)(dt_w + (size_t)d*DTR + j*4);
    float b = dt_b[d];
    __syncthreads();
#pragma unroll 4
    for (int row = 0; row < 32; row++) {
        float acc = b;
#pragma unroll
        for (int j = 0; j < 8; j++) {
            float4 x4 = *(const float4*)&xs[row][j*4];
            acc = fmaf(wr[j].x, x4.x, acc);
            acc = fmaf(wr[j].y, x4.y, acc);
            acc = fmaf(wr[j].z, x4.z, acc);
            acc = fmaf(wr[j].w, x4.w, acc);
        }
        delta[(size_t)(m0 + row) * DI + d] = softplusf(acc);
    }
}

// ======== selective scan + gate: smem-staged (32 timesteps/stage, cp.async) ========
// block = (dir, b, 32 d's), 128 threads: q = t&3 (4 states each), dd = t>>2
#define SCT 32
__global__ __launch_bounds__(128)
void scan_k(const float* __restrict__ delta, const bf* __restrict__ u,
            const float* __restrict__ xsum, const bf* __restrict__ xz,
            const float* __restrict__ Af, const float* __restrict__ Df,
            const float* __restrict__ Ab, const float* __restrict__ Db,
            bf* __restrict__ y) {
    __shared__ __align__(16) float s_de[2][SCT][32];
    __shared__ __align__(16) bf    s_u[2][SCT][32];
    __shared__ __align__(16) bf    s_z[2][SCT][32];
    __shared__ __align__(16) float s_bc[2][SCT][32];
    __shared__ __align__(16) bf    s_y[SCT][32];

    int dir = blockIdx.z, b = blockIdx.y;
    int d0 = blockIdx.x * 32;
    int t = threadIdx.x;
    int q = t & 3, dd = t >> 2;
    int d = d0 + dd;

    const float* A_log = dir ? Ab : Af;
    const float* Dv    = dir ? Db : Df;
    float aa[4];
#pragma unroll
    for (int n = 0; n < 4; n++)
        aa[n] = -__expf(A_log[d * DS + q*4 + n]) * 1.4426950408889634f;
    float Dd = Dv[d];
    float h[4];
#pragma unroll
    for (int n = 0; n < 4; n++) h[n] = 0.0f;

    size_t base = (size_t)b * SEQL;
    const float* pd  = delta + (size_t)dir*BL*DI  + base*DI  + d0;
    const bf*    pu  = u     + (size_t)dir*BL*DI  + base*DI  + d0;
    const bf*    pz  = xz    + (size_t)dir*BL*XZW + base*XZW + DI + d0;
    const float* pbc = xsum  + (size_t)dir*BL*64  + base*64  + 32;
    bf*          py  = y + base*2048 + dir*1024 + d0;

    // stage loader: 32 timesteps starting at l0 into buffer buf
    auto stload = [&](int buf, int l0) {
        // delta: 32 rows x 128B (8 chunks/row) -> 256 chunks, 2/thread
#pragma unroll
        for (int i = 0; i < 2; i++) {
            int c = t + i*128, row = c >> 3, seg = c & 7;
            cp16u((uint32_t)__cvta_generic_to_shared(&s_de[buf][row][seg*4]),
                  pd + (size_t)(l0 + row)*DI + seg*4);
        }
        // u: 32 rows x 64B (4 chunks/row) -> 128 chunks
        {
            int row = t >> 2, seg = t & 3;
            cp16u((uint32_t)__cvta_generic_to_shared(&s_u[buf][row][seg*8]),
                  pu + (size_t)(l0 + row)*DI + seg*8);
        }
        // z: same shape
        {
            int row = t >> 2, seg = t & 3;
            cp16u((uint32_t)__cvta_generic_to_shared(&s_z[buf][row][seg*8]),
                  pz + (size_t)(l0 + row)*XZW + seg*8);
        }
        // B/C: 32 rows x 128B
#pragma unroll
        for (int i = 0; i < 2; i++) {
            int c = t + i*128, row = c >> 3, seg = c & 7;
            cp16u((uint32_t)__cvta_generic_to_shared(&s_bc[buf][row][seg*4]),
                  pbc + (size_t)(l0 + row)*64 + seg*4);
        }
        cpcommit();
    };

    stload(0, 0);
    const int nst = SEQL / SCT;    // 32
    for (int st = 0; st < nst; st++) {
        cpwait<0>();
        __syncthreads();
        int buf = st & 1;
        if (st + 1 < nst) stload(buf ^ 1, (st + 1) * SCT);
#pragma unroll 4
        for (int s = 0; s < SCT; s++) {
            float de = s_de[buf][s][dd];
            float uu = __bfloat162float(s_u[buf][s][dd]);
            float du = de * uu;
            float4 Bv = *(const float4*)&s_bc[buf][s][q*4];
            float4 Cv = *(const float4*)&s_bc[buf][s][16 + q*4];
            const float* Bf = (const float*)&Bv;
            const float* Cf = (const float*)&Cv;
            float a0 = 0.0f, a1 = 0.0f;
#pragma unroll
            for (int n = 0; n < 4; n++) {
                float dA = exp2f(de * aa[n]);
                h[n] = fmaf(dA, h[n], du * Bf[n]);
                float tt = h[n] * Cf[n];
                if (n & 1) a1 += tt; else a0 += tt;
            }
            float part = a0 + a1;
            part += __shfl_xor_sync(0xffffffffu, part, 1);
            part += __shfl_xor_sync(0xffffffffu, part, 2);
            if (q == 0) {
                float z0 = __bfloat162float(s_z[buf][s][dd]);
                float yy = part + uu * Dd;
                float sg = z0 / (1.0f + __expf(-z0));
                s_y[s][dd] = __float2bfloat16(yy * sg);
            }
        }
        __syncthreads();
        // cooperative coalesced store of 32 rows x 64B
        {
            int row = t >> 2, seg = t & 3;
            uint4 v = *(const uint4*)&s_y[row][seg*8];
            *(uint4*)(py + (size_t)(st*SCT + row)*2048 + seg*8) = v;
        }
    }
}

// ---------------- launch ----------------
template <typename T>
static T* symp(const void* sym) {
    void* p = nullptr;
    cudaGetSymbolAddress(&p, sym);
    return (T*)p;
}

#define SMEM2_128 (2 * 256 * KST * 2)   // 73728
#define SMEM2_64  (2 * 192 * KST * 2)   // 55296

extern "C" void kernel_launch(void* const* d_in, const int* in_sizes, int n_in,
                              void* d_out, int out_size) {
    const int*           x      = (const int*)d_in[0];
    const unsigned char* m      = (const unsigned char*)d_in[2];
    const float*         emb    = (const float*)d_in[3];
    const float*         conv_w = (const float*)d_in[4];
    const float*         conv_b = (const float*)d_in[5];
    const float*         ln_g   = (const float*)d_in[6];
    const float*         ln_b   = (const float*)d_in[7];
    const float*         proj_b = (const float*)d_in[9];
    float* out = (float*)d_out;

    bf*    h    = symp<bf>(g_h);
    float* tmp  = symp<float>(g_tmp);
    bf*    xz   = symp<bf>(g_xz);
    bf*    u    = symp<bf>(g_u);
    float* dl   = symp<float>(g_delta);
    float* xdbc = symp<float>(g_xdbc);
    float* xs   = symp<float>(g_xs);
    bf*    y    = symp<bf>(g_y);
    bf*    cwt  = symp<bf>(g_cwt);
    bf*    inw  = symp<bf>(g_inw);
    bf*    xw   = symp<bf>(g_xw);
    bf*    owT  = symp<bf>(g_owT);
    bf*    prw  = symp<bf>(g_projw);
    bf*    wfu  = symp<bf>(g_wfuse);

    cudaFuncSetAttribute(conv256, cudaFuncAttributeMaxDynamicSharedMemorySize, SMEM2_128);
    cudaFuncSetAttribute((const void*)gemm256<0>, cudaFuncAttributeMaxDynamicSharedMemorySize, SMEM2_128);
    cudaFuncSetAttribute((const void*)gemm256<1>, cudaFuncAttributeMaxDynamicSharedMemorySize, SMEM2_128);
    cudaFuncSetAttribute(gemm_xd, cudaFuncAttributeMaxDynamicSharedMemorySize, SMEM2_64);

    // 1: merged weight conversion
    {
        CvtP p;
        p.s[0] = (const float*)d_in[10];  p.d[0] = inw;
        p.s[1] = (const float*)d_in[19];  p.d[1] = inw + (size_t)XZW*CH;
        p.s[2] = (const float*)d_in[13];  p.d[2] = xw;
        p.s[3] = (const float*)d_in[22];  p.d[3] = xw + (size_t)64*DI;
        p.s[4] = (const float*)d_in[8];   p.d[4] = prw;
        p.owf  = (const float*)d_in[18];
        p.owb  = (const float*)d_in[27];
        cvt_all<<<3*CH + 256 + 2768, 256>>>(conv_w, p);
    }
    // 2: Wfuse
    gemm256<0><<<dim3(DI/128, CH/128, 2), 256, SMEM2_128>>>(
        prw, owT, wfu, CH, 2*CH, CH, 2048, 0,
        (size_t)CH, (size_t)DI*CH, (size_t)DI);
    // 3: embedding
    embed_k<<<(BL*CH + 255)/256, 256>>>(x, emb, h);

    // 4-9: conv stack (launch #6 = conv layer 1 for ncu capture)
    for (int layer = 0; layer < 3; layer++) {
        conv256<<<dim3(CH/128, BL/128, 2), 256, SMEM2_128>>>(
            h, cwt + (size_t)layer*KW*CH*CH, tmp);
        ln_k<<<BL, 128>>>(tmp, conv_b + layer*CH, ln_g + layer*CH, ln_b + layer*CH, m, h);
    }

    const float* mcwf = (const float*)d_in[11];
    const float* mcbf = (const float*)d_in[12];
    const float* mcwb = (const float*)d_in[20];
    const float* mcbb = (const float*)d_in[21];
    const float* dtwf = (const float*)d_in[14];
    const float* dtbf = (const float*)d_in[15];
    const float* dtwb = (const float*)d_in[23];
    const float* dtbb = (const float*)d_in[24];
    const float* Alf  = (const float*)d_in[16];
    const float* Dvf  = (const float*)d_in[17];
    const float* Alb  = (const float*)d_in[25];
    const float* Dvb  = (const float*)d_in[26];

    // in-proj
    gemm256<0><<<dim3(XZW/128, BL/128, 2), 256, SMEM2_128>>>(
        h, inw, xz, CH, CH, CH, XZW, 1,
        0, (size_t)XZW*CH, (size_t)BL*XZW);
    // depthwise conv + silu
    dwconv_k<<<(2*BL*DI + 255)/256, 256>>>(xz, mcwf, mcbf, mcwb, mcbb, u);
    // xdbc partials
    gemm_xd<<<dim3(1, BL/128, 4), 128, SMEM2_64>>>(u, xw, xdbc, 512);
    // delta (+ B/C combine)
    dt_k<<<dim3(DI/256, BL/32, 2), 256>>>(xdbc, dtwf, dtbf, dtwb, dtbb, dl, xs);
    // selective scan + gate (smem-staged)
    scan_k<<<dim3(DI/32, BATCH, 2), 128>>>(dl, u, xs, xz, Alf, Dvf, Alb, Dvb, y);
    // fused out-proj + final projection
    gemm256<1><<<dim3(CH/128, BL/128, 2), 256, SMEM2_128>>>(
        y, wfu, tmp, 1024, 2048, 2048, CH, 0,
        (size_t)1024, (size_t)1024, (size_t)BL*CH);
    // combine partials + bias + mask -> out
    comb_k<<<(BL*CH/4 + 255)/256, 256>>>(tmp, proj_b, m, out);
}